// round 4
// baseline (speedup 1.0000x reference)
#include <cuda_runtime.h>
#include <cuda_bf16.h>
#include <mma.h>
#include <math.h>

using namespace nvcuda;

#define HH 128
#define WW 224
#define NN 4
#define HW (HH*WW)   // 28672

// ---------------- scratch (static __device__ globals) -----------------------
__device__ float g_Ar[(size_t)NN*144*HW];
__device__ float g_Ai[(size_t)NN*144*HW];
__device__ float g_Br[(size_t)NN*144*HW];
__device__ float g_Bi[(size_t)NN*144*HW];
__device__ float g_mr[144], g_sr[144], g_mi[144], g_si[144];
__device__ float2 g_partR[144*16];
__device__ float2 g_partI[144*16];

// GEMM-layout weights, split bf16 (hi/lo)
__device__ __nv_bfloat16 g_B1h[2304*288], g_B1l[2304*288];
__device__ __nv_bfloat16 g_B2h[2592*192], g_B2l[2592*192];
__device__ __nv_bfloat16 g_B3h[1728*192], g_B3l[1728*192];
__device__ __nv_bfloat16 g_B4h[1728*192], g_B4l[1728*192];

// ---------------- weight matrix builders ------------------------------------
// Real-input layer: k = ci*9+tap, n = 2*co+part; B[k][n] = part? wi : wr
__global__ void build_B_real(const float* __restrict__ wr,
                             const float* __restrict__ wi,
                             __nv_bfloat16* __restrict__ Bh,
                             __nv_bfloat16* __restrict__ Bl,
                             int Cin, int Cout)
{
    int Neff = 2*Cout;
    int total = Cin*9*Neff;
    int idx = blockIdx.x*256 + threadIdx.x;
    if (idx >= total) return;
    int n = idx % Neff, k = idx / Neff;
    int ci = k/9, tap = k - ci*9;
    int co = n >> 1, part = n & 1;
    const float* w = part ? wi : wr;
    float v = w[((size_t)co*Cin + ci)*9 + tap];
    __nv_bfloat16 h = __float2bfloat16(v);
    Bh[idx] = h;
    Bl[idx] = __float2bfloat16(v - __bfloat162float(h));
}

// Complex layer: k = (2*ci+cplx)*9+tap, n = 2*co+part
// R = ar*wr - ai*wi ; I = ar*wi + ai*wr
__global__ void build_B_cplx(const float* __restrict__ wr,
                             const float* __restrict__ wi,
                             __nv_bfloat16* __restrict__ Bh,
                             __nv_bfloat16* __restrict__ Bl,
                             int Cin, int Cout)
{
    int Neff = 2*Cout;
    int total = 2*Cin*9*Neff;
    int idx = blockIdx.x*256 + threadIdx.x;
    if (idx >= total) return;
    int n = idx % Neff, k = idx / Neff;
    int cc = k/9, tap = k - cc*9;
    int ci = cc >> 1, cplx = cc & 1;
    int co = n >> 1, part = n & 1;
    float wrv = wr[((size_t)co*Cin + ci)*9 + tap];
    float wiv = wi[((size_t)co*Cin + ci)*9 + tap];
    float v = (part == 0) ? (cplx == 0 ?  wrv : -wiv)
                          : (cplx == 0 ?  wiv :  wrv);
    __nv_bfloat16 h = __float2bfloat16(v);
    Bh[idx] = h;
    Bl[idx] = __float2bfloat16(v - __bfloat162float(h));
}

// ---------------- tensor-core implicit-GEMM conv ----------------------------
// Block = one image row (224 pixels) x Ncols output columns.
// 448 threads = 14 warps; warp w owns pixels [16w, 16w+16) x all Ncols.
// A staged via on-the-fly im2col into smem [32 k][232] bf16 (hi+lo split),
// B staged [32 k][Ncols] bf16 (hi+lo). 3-pass mma: ah*bh + ah*bl + al*bh.
template<int NFRAG, bool CPLX>
__global__ __launch_bounds__(448, 1)
void conv_gemm(const float* __restrict__ xr, const float* __restrict__ xi,
               const __nv_bfloat16* __restrict__ Bgh,
               const __nv_bfloat16* __restrict__ Bgl,
               float* __restrict__ yr, float* __restrict__ yi,
               int Cin, int Cout, int Keff, int Neff)
{
    constexpr int Ncols = NFRAG*16;
    extern __shared__ char smc[];
    __nv_bfloat16* sAh = (__nv_bfloat16*)smc;             // [32][232]
    __nv_bfloat16* sAl = (__nv_bfloat16*)(smc + 14848);   // [32][232]
    __nv_bfloat16* sBh = (__nv_bfloat16*)(smc + 29696);   // [32][Ncols]
    __nv_bfloat16* sBl = (__nv_bfloat16*)(smc + 29696 + 64*Ncols);
    float* sD = (float*)smc;                              // [224][20] (reused)

    const int t   = threadIdx.x;
    const int wid = t >> 5;               // 0..13 -> m-tile
    const int rowb = blockIdx.x;          // 0..511 (image row)
    const int n_img = rowb / HH;
    const int h     = rowb % HH;
    const int nb    = blockIdx.y * Ncols; // base output column

    wmma::fragment<wmma::accumulator, 16,16,16, float> acc[NFRAG];
#pragma unroll
    for (int f = 0; f < NFRAG; ++f) wmma::fill_fragment(acc[f], 0.f);

    const int p  = t % 224;
    const int kq = t / 224;   // 0 or 1

    for (int k0 = 0; k0 < Keff; k0 += 32) {
        // ---- im2col A chunk (hi/lo split) ----
        for (int kk = kq; kk < 32; kk += 2) {
            int k = k0 + kk;
            int cc = k / 9, tap = k - cc*9;
            int dh = tap/3 - 1, dw = tap - (tap/3)*3 - 1;
            const float* plane;
            if (CPLX)
                plane = ((cc & 1) ? xi : xr) + ((size_t)(n_img*Cin + (cc >> 1)))*HW;
            else
                plane = xr + ((size_t)(n_img*Cin + cc))*HW;
            int h2 = h + dh, w2 = p + dw;
            float v = 0.f;
            if (((unsigned)h2 < HH) && ((unsigned)w2 < WW))
                v = plane[h2*WW + w2];
            __nv_bfloat16 hi = __float2bfloat16(v);
            sAh[kk*232 + p] = hi;
            sAl[kk*232 + p] = __float2bfloat16(v - __bfloat162float(hi));
        }
        // ---- B chunk ----
        for (int e = t; e < 32*Ncols; e += 448) {
            int r = e / Ncols, c = e - r*Ncols;
            size_t gi = (size_t)(k0 + r)*Neff + nb + c;
            sBh[e] = Bgh[gi];
            sBl[e] = Bgl[gi];
        }
        __syncthreads();

        // ---- 2 k-steps of 16, 3-pass mma ----
#pragma unroll
        for (int ks = 0; ks < 2; ++ks) {
            wmma::fragment<wmma::matrix_a,16,16,16,__nv_bfloat16,wmma::col_major> ah, al;
            wmma::load_matrix_sync(ah, sAh + ks*16*232 + wid*16, 232);
            wmma::load_matrix_sync(al, sAl + ks*16*232 + wid*16, 232);
#pragma unroll
            for (int f = 0; f < NFRAG; ++f) {
                wmma::fragment<wmma::matrix_b,16,16,16,__nv_bfloat16,wmma::row_major> bh, bl;
                wmma::load_matrix_sync(bh, sBh + ks*16*Ncols + f*16, Ncols);
                wmma::load_matrix_sync(bl, sBl + ks*16*Ncols + f*16, Ncols);
                wmma::mma_sync(acc[f], ah, bh, acc[f]);
                wmma::mma_sync(acc[f], ah, bl, acc[f]);
                wmma::mma_sync(acc[f], al, bh, acc[f]);
            }
        }
        __syncthreads();
    }

    // ---- epilogue: wave per fragment through sD[224][20] ----
#pragma unroll
    for (int g = 0; g < NFRAG; ++g) {
        wmma::store_matrix_sync(sD + wid*16*20, acc[g], 20, wmma::mem_row_major);
        __syncthreads();
        for (int e = t; e < 224*16; e += 448) {
            int c = e / 224, pp = e - c*224;
            int ng = nb + g*16 + c;
            int co = ng >> 1;
            float* dst = ((ng & 1) ? yi : yr)
                       + ((size_t)(n_img*Cout + co))*HW + h*WW + pp;
            *dst = sD[pp*20 + c];
        }
        __syncthreads();
    }
}

// ---------------- BN stats, stage 1 -----------------------------------------
#define SPLIT 4
#define CHUNK (HW/SPLIT)
__global__ void bn_stats1(const float* __restrict__ x, int C,
                          float2* __restrict__ part)
{
    const int c = blockIdx.x, y = blockIdx.y;
    const int n = y >> 2, chunk = y & 3;
    const int t = threadIdx.x;
    const float4* p = reinterpret_cast<const float4*>(
        x + ((size_t)(n*C + c))*HW + (size_t)chunk*CHUNK);
    float s = 0.f, q = 0.f;
    for (int i = t; i < CHUNK/4; i += 256) {
        float4 v = p[i];
        s += v.x + v.y + v.z + v.w;
        q = fmaf(v.x, v.x, q); q = fmaf(v.y, v.y, q);
        q = fmaf(v.z, v.z, q); q = fmaf(v.w, v.w, q);
    }
    __shared__ float ss[256], sq[256];
    ss[t] = s; sq[t] = q;
    __syncthreads();
    for (int o = 128; o > 0; o >>= 1) {
        if (t < o) { ss[t] += ss[t+o]; sq[t] += sq[t+o]; }
        __syncthreads();
    }
    if (t == 0) part[c*(NN*SPLIT) + y] = make_float2(ss[0], sq[0]);
}

// ---------------- BN stats, stage 2 -----------------------------------------
__global__ void bn_stats2(const float2* __restrict__ part,
                          float* __restrict__ mean, float* __restrict__ rstd)
{
    const int c = blockIdx.x;
    if (threadIdx.x == 0) {
        double s = 0.0, q = 0.0;
        for (int i = 0; i < NN*SPLIT; ++i) {
            float2 v = part[c*(NN*SPLIT) + i];
            s += (double)v.x; q += (double)v.y;
        }
        double cnt = (double)NN * HW;
        double m = s / cnt;
        double var = q / cnt - m*m;
        mean[c] = (float)m;
        rstd[c] = (float)(1.0 / sqrt(var + 1e-5));
    }
}

// ---------------- BN apply + ReLU -------------------------------------------
__global__ void bn_apply_relu4(float* __restrict__ x, int C,
                               const float* __restrict__ mean,
                               const float* __restrict__ rstd,
                               const float* __restrict__ g,
                               const float* __restrict__ b)
{
    const int c = blockIdx.y, n = blockIdx.z;
    const float sc = rstd[c] * g[c];
    const float bi = b[c] - mean[c] * sc;
    float4* p = reinterpret_cast<float4*>(x + ((size_t)(n*C + c))*HW);
    int i = blockIdx.x*256 + threadIdx.x;
    float4 v = p[i];
    v.x = fmaxf(fmaf(v.x, sc, bi), 0.f);
    v.y = fmaxf(fmaf(v.y, sc, bi), 0.f);
    v.z = fmaxf(fmaf(v.z, sc, bi), 0.f);
    v.w = fmaxf(fmaf(v.w, sc, bi), 0.f);
    p[i] = v;
}

// ------- layer-4 fused: BN(r), BN(i), ReLU, |z| -> m -------------------------
__global__ void bn_relu_mag4(const float* __restrict__ xr,
                             const float* __restrict__ xi,
                             float* __restrict__ m, int C,
                             const float* __restrict__ mr, const float* __restrict__ sr,
                             const float* __restrict__ mi, const float* __restrict__ si,
                             const float* __restrict__ g,  const float* __restrict__ b)
{
    const int c = blockIdx.y, n = blockIdx.z;
    const float scr = sr[c] * g[c];
    const float bir = b[c] - mr[c] * scr;
    const float sci = si[c] * g[c];
    const float bii = b[c] - mi[c] * sci;
    size_t base = ((size_t)(n*C + c))*HW;
    const float4* pr = reinterpret_cast<const float4*>(xr + base);
    const float4* pi = reinterpret_cast<const float4*>(xi + base);
    float4* pm = reinterpret_cast<float4*>(m + base);
    int i = blockIdx.x*256 + threadIdx.x;
    float4 vr = pr[i], vi = pi[i], vo;
    float a, bb;
    a = fmaxf(fmaf(vr.x, scr, bir), 0.f); bb = fmaxf(fmaf(vi.x, sci, bii), 0.f);
    vo.x = sqrtf(a*a + bb*bb);
    a = fmaxf(fmaf(vr.y, scr, bir), 0.f); bb = fmaxf(fmaf(vi.y, sci, bii), 0.f);
    vo.y = sqrtf(a*a + bb*bb);
    a = fmaxf(fmaf(vr.z, scr, bir), 0.f); bb = fmaxf(fmaf(vi.z, sci, bii), 0.f);
    vo.z = sqrtf(a*a + bb*bb);
    a = fmaxf(fmaf(vr.w, scr, bir), 0.f); bb = fmaxf(fmaf(vi.w, sci, bii), 0.f);
    vo.w = sqrtf(a*a + bb*bb);
    pm[i] = vo;
}

// ---------------- head: 96 -> 3 channels (scalar fp32) ----------------------
__global__ __launch_bounds__(256)
void conv_head(const float* __restrict__ m,
               const float* __restrict__ wc, const float* __restrict__ bc,
               const float* __restrict__ wg, const float* __restrict__ bg,
               float* __restrict__ out)
{
    __shared__ float sm[18*35];
    __shared__ float sw[3*9];
    const int t = threadIdx.x;
    const int tx = t & 15, ty = t >> 4;
    const int wbase = blockIdx.x * 32, hbase = blockIdx.y * 16;
    const int n = blockIdx.z;

    float acc[3][2] = {};
    for (int ci = 0; ci < 96; ++ci) {
        const float* p = m + ((size_t)(n*96 + ci))*HW;
        for (int idx = t; idx < 18*34; idx += 256) {
            int r = idx / 34, c = idx - r*34;
            int gh = hbase - 1 + r, gw = wbase - 1 + c;
            sm[r*35 + c] = (((unsigned)gh < HH) && ((unsigned)gw < WW))
                           ? p[gh*WW + gw] : 0.f;
        }
        if (t < 27) {
            int co = t / 9, k = t - co*9;
            sw[t] = (co == 0) ? wc[(size_t)ci*9 + k]
                              : wg[((size_t)(co-1)*96 + ci)*9 + k];
        }
        __syncthreads();
#pragma unroll
        for (int kh = 0; kh < 3; ++kh)
#pragma unroll
            for (int kw = 0; kw < 3; ++kw) {
                float a0 = sm[(ty+kh)*35 + 2*tx + kw];
                float a1 = sm[(ty+kh)*35 + 2*tx + kw + 1];
#pragma unroll
                for (int co = 0; co < 3; ++co) {
                    float wv = sw[co*9 + kh*3 + kw];
                    acc[co][0] = fmaf(a0, wv, acc[co][0]);
                    acc[co][1] = fmaf(a1, wv, acc[co][1]);
                }
            }
        __syncthreads();
    }
    const int h = hbase + ty, w0 = wbase + 2*tx;
    const float b0 = bc[0], b1 = bg[0], b2 = bg[1];
    float c0a = acc[0][0] + b0, c0b = acc[0][1] + b0;
    c0a = 1.f / (1.f + expf(-c0a));
    c0b = 1.f / (1.f + expf(-c0b));
    size_t o0 = ((size_t)(n*3 + 0))*HW + h*WW + w0;
    size_t o1 = ((size_t)(n*3 + 1))*HW + h*WW + w0;
    size_t o2 = ((size_t)(n*3 + 2))*HW + h*WW + w0;
    out[o0] = c0a;            out[o0+1] = c0b;
    out[o1] = acc[1][0] + b1; out[o1+1] = acc[1][1] + b1;
    out[o2] = acc[2][0] + b2; out[o2+1] = acc[2][1] + b2;
}

// ---------------- driver -----------------------------------------------------
extern "C" void kernel_launch(void* const* d_in, const int* in_sizes, int n_in,
                              void* d_out, int out_size)
{
    (void)in_sizes; (void)n_in; (void)out_size;
    const float* x   = (const float*)d_in[0];
    const float* w1r = (const float*)d_in[1];
    const float* w1i = (const float*)d_in[2];
    const float* g1  = (const float*)d_in[3];
    const float* b1  = (const float*)d_in[4];
    const float* w2r = (const float*)d_in[5];
    const float* w2i = (const float*)d_in[6];
    const float* g2  = (const float*)d_in[7];
    const float* b2  = (const float*)d_in[8];
    const float* w3r = (const float*)d_in[9];
    const float* w3i = (const float*)d_in[10];
    const float* g3  = (const float*)d_in[11];
    const float* b3  = (const float*)d_in[12];
    const float* w4r = (const float*)d_in[13];
    const float* w4i = (const float*)d_in[14];
    const float* g4  = (const float*)d_in[15];
    const float* b4  = (const float*)d_in[16];
    const float* wc  = (const float*)d_in[17];
    const float* bc  = (const float*)d_in[18];
    const float* wg  = (const float*)d_in[19];
    const float* bg  = (const float*)d_in[20];
    float* out = (float*)d_out;

    float *Ar, *Ai, *Br, *Bi, *mr, *sr, *mi, *si;
    float2 *pR, *pI;
    __nv_bfloat16 *B1h, *B1l, *B2h, *B2l, *B3h, *B3l, *B4h, *B4l;
    cudaGetSymbolAddress((void**)&Ar, g_Ar);
    cudaGetSymbolAddress((void**)&Ai, g_Ai);
    cudaGetSymbolAddress((void**)&Br, g_Br);
    cudaGetSymbolAddress((void**)&Bi, g_Bi);
    cudaGetSymbolAddress((void**)&mr, g_mr);
    cudaGetSymbolAddress((void**)&sr, g_sr);
    cudaGetSymbolAddress((void**)&mi, g_mi);
    cudaGetSymbolAddress((void**)&si, g_si);
    cudaGetSymbolAddress((void**)&pR, g_partR);
    cudaGetSymbolAddress((void**)&pI, g_partI);
    cudaGetSymbolAddress((void**)&B1h, g_B1h);
    cudaGetSymbolAddress((void**)&B1l, g_B1l);
    cudaGetSymbolAddress((void**)&B2h, g_B2h);
    cudaGetSymbolAddress((void**)&B2l, g_B2l);
    cudaGetSymbolAddress((void**)&B3h, g_B3h);
    cudaGetSymbolAddress((void**)&B3l, g_B3l);
    cudaGetSymbolAddress((void**)&B4h, g_B4h);
    cudaGetSymbolAddress((void**)&B4l, g_B4l);

    static int attr_done = 0;
    if (!attr_done) {
        cudaFuncSetAttribute((const void*)conv_gemm<9,false>,
                             cudaFuncAttributeMaxDynamicSharedMemorySize, 48128);
        cudaFuncSetAttribute((const void*)conv_gemm<12,true>,
                             cudaFuncAttributeMaxDynamicSharedMemorySize, 54272);
        attr_done = 1;
    }

    // Weight matrices (tiny; rebuilt every call, deterministic)
    build_B_real<<<(2304*288 + 255)/256, 256>>>(w1r, w1i, B1h, B1l, 256, 144);
    build_B_cplx<<<(2592*192 + 255)/256, 256>>>(w2r, w2i, B2h, B2l, 144, 96);
    build_B_cplx<<<(1728*192 + 255)/256, 256>>>(w3r, w3i, B3h, B3l, 96, 96);
    build_B_cplx<<<(1728*192 + 255)/256, 256>>>(w4r, w4i, B4h, B4l, 96, 96);

    const dim3 blk(256);

    // Layer 1: real input (256 -> 144), N split in 2
    conv_gemm<9,false><<<dim3(512, 2), 448, 48128>>>(x, nullptr, B1h, B1l,
                                                     Ar, Ai, 256, 144, 2304, 288);
    bn_stats1<<<dim3(144, NN*SPLIT), blk>>>(Ar, 144, pR);
    bn_stats1<<<dim3(144, NN*SPLIT), blk>>>(Ai, 144, pI);
    bn_stats2<<<144, 32>>>(pR, mr, sr);
    bn_stats2<<<144, 32>>>(pI, mi, si);
    bn_apply_relu4<<<dim3(28, 144, NN), blk>>>(Ar, 144, mr, sr, g1, b1);
    bn_apply_relu4<<<dim3(28, 144, NN), blk>>>(Ai, 144, mi, si, g1, b1);

    // Layer 2: complex (144 -> 96)
    conv_gemm<12,true><<<dim3(512, 1), 448, 54272>>>(Ar, Ai, B2h, B2l,
                                                     Br, Bi, 144, 96, 2592, 192);
    bn_stats1<<<dim3(96, NN*SPLIT), blk>>>(Br, 96, pR);
    bn_stats1<<<dim3(96, NN*SPLIT), blk>>>(Bi, 96, pI);
    bn_stats2<<<96, 32>>>(pR, mr, sr);
    bn_stats2<<<96, 32>>>(pI, mi, si);
    bn_apply_relu4<<<dim3(28, 96, NN), blk>>>(Br, 96, mr, sr, g2, b2);
    bn_apply_relu4<<<dim3(28, 96, NN), blk>>>(Bi, 96, mi, si, g2, b2);

    // Layer 3: complex (96 -> 96)
    conv_gemm<12,true><<<dim3(512, 1), 448, 54272>>>(Br, Bi, B3h, B3l,
                                                     Ar, Ai, 96, 96, 1728, 192);
    bn_stats1<<<dim3(96, NN*SPLIT), blk>>>(Ar, 96, pR);
    bn_stats1<<<dim3(96, NN*SPLIT), blk>>>(Ai, 96, pI);
    bn_stats2<<<96, 32>>>(pR, mr, sr);
    bn_stats2<<<96, 32>>>(pI, mi, si);
    bn_apply_relu4<<<dim3(28, 96, NN), blk>>>(Ar, 96, mr, sr, g3, b3);
    bn_apply_relu4<<<dim3(28, 96, NN), blk>>>(Ai, 96, mi, si, g3, b3);

    // Layer 4: complex (96 -> 96), then fused BN+ReLU+|z| into Ar
    conv_gemm<12,true><<<dim3(512, 1), 448, 54272>>>(Ar, Ai, B4h, B4l,
                                                     Br, Bi, 96, 96, 1728, 192);
    bn_stats1<<<dim3(96, NN*SPLIT), blk>>>(Br, 96, pR);
    bn_stats1<<<dim3(96, NN*SPLIT), blk>>>(Bi, 96, pI);
    bn_stats2<<<96, 32>>>(pR, mr, sr);
    bn_stats2<<<96, 32>>>(pI, mi, si);
    bn_relu_mag4<<<dim3(28, 96, NN), blk>>>(Br, Bi, Ar, 96,
                                            mr, sr, mi, si, g4, b4);

    // head (ch0 sigmoid)
    conv_head<<<dim3(7, 8, NN), blk>>>(Ar, wc, bc, wg, bg, out);
}

// round 6
// speedup vs baseline: 2.4842x; 2.4842x over previous
#include <cuda_runtime.h>
#include <cuda_bf16.h>
#include <mma.h>
#include <math.h>
#include <cstdint>

using namespace nvcuda;

#define HH 128
#define WW 224
#define NN 4
#define HW (HH*WW)          // 28672
#define PTOT (NN*HW)        // 114688

// ---------------- scratch (__device__ globals, 16B aligned) -----------------
__device__ __align__(16) float         g_Y [(size_t)PTOT*288];
__device__ __align__(16) __nv_bfloat16 g_Xh[(size_t)PTOT*288];
__device__ __align__(16) __nv_bfloat16 g_Xl[(size_t)PTOT*288];
__device__ __align__(16) float         g_M [(size_t)PTOT*96];
__device__ float  g_mean[288], g_rstd[288];
__device__ float2 g_part[288*224];

// weights, layout [tap][k][n], split bf16 hi/lo
__device__ __align__(16) __nv_bfloat16 g_B1h[9*256*288], g_B1l[9*256*288];
__device__ __align__(16) __nv_bfloat16 g_B2h[9*288*192], g_B2l[9*288*192];
__device__ __align__(16) __nv_bfloat16 g_B3h[9*192*192], g_B3l[9*192*192];
__device__ __align__(16) __nv_bfloat16 g_B4h[9*192*192], g_B4l[9*192*192];

// ---------------- cp.async helpers ------------------------------------------
__device__ __forceinline__ void cp16(uint32_t s, const void* g, int sz) {
    asm volatile("cp.async.cg.shared.global [%0], [%1], 16, %2;"
                 :: "r"(s), "l"(g), "r"(sz));
}
#define CP_COMMIT() asm volatile("cp.async.commit_group;" ::: "memory")
#define CP_WAIT1()  asm volatile("cp.async.wait_group 1;" ::: "memory")

// ---------------- weight builders -------------------------------------------
__global__ void build_real(const float* __restrict__ wr,
                           const float* __restrict__ wi,
                           __nv_bfloat16* __restrict__ Bh,
                           __nv_bfloat16* __restrict__ Bl,
                           int Cin, int Cout)
{
    int Neff = 2*Cout;
    int total = 9*Cin*Neff;
    int idx = blockIdx.x*256 + threadIdx.x;
    if (idx >= total) return;
    int n = idx % Neff; int kk = idx / Neff;
    int k = kk % Cin;   int tap = kk / Cin;
    int co = n >> 1, part = n & 1;
    float v = (part ? wi : wr)[((size_t)co*Cin + k)*9 + tap];
    __nv_bfloat16 h = __float2bfloat16(v);
    Bh[idx] = h;
    Bl[idx] = __float2bfloat16(v - __bfloat162float(h));
}

__global__ void build_cplx(const float* __restrict__ wr,
                           const float* __restrict__ wi,
                           __nv_bfloat16* __restrict__ Bh,
                           __nv_bfloat16* __restrict__ Bl,
                           int Cin, int Cout)
{
    int Neff = 2*Cout, Ktot = 2*Cin;
    int total = 9*Ktot*Neff;
    int idx = blockIdx.x*256 + threadIdx.x;
    if (idx >= total) return;
    int n = idx % Neff; int kk = idx / Neff;
    int k2 = kk % Ktot;  int tap = kk / Ktot;
    int ci = k2 >> 1, cplx = k2 & 1;
    int co = n >> 1,  part = n & 1;
    float wrv = wr[((size_t)co*Cin + ci)*9 + tap];
    float wiv = wi[((size_t)co*Cin + ci)*9 + tap];
    float v = (part == 0) ? (cplx == 0 ?  wrv : -wiv)
                          : (cplx == 0 ?  wiv :  wrv);
    __nv_bfloat16 h = __float2bfloat16(v);
    Bh[idx] = h;
    Bl[idx] = __float2bfloat16(v - __bfloat162float(h));
}

// ---------------- input transpose: x NCHW fp32 -> X0 NHWC bf16 hi/lo --------
__global__ void tr_in(const float* __restrict__ x,
                      __nv_bfloat16* __restrict__ Xh,
                      __nv_bfloat16* __restrict__ Xl)
{
    __shared__ float sT[32][65];
    const int t = threadIdx.x;
    const int gp = blockIdx.x * 64;
    const int cb = blockIdx.y * 32;
    const int n = gp / HW, rbas = gp % HW;
#pragma unroll
    for (int it = 0; it < 8; ++it) {
        int idx = t + it*256;
        int cc = idx >> 6, pp = idx & 63;
        sT[cc][pp] = x[((size_t)(n*256 + cb + cc))*HW + rbas + pp];
    }
    __syncthreads();
#pragma unroll
    for (int it = 0; it < 8; ++it) {
        int idx = t + it*256;
        int cc = idx & 31, pp = idx >> 5;
        float v = sT[cc][pp];
        __nv_bfloat16 h = __float2bfloat16(v);
        size_t o = (size_t)(gp + pp)*256 + cb + cc;
        Xh[o] = h;
        Xl[o] = __float2bfloat16(v - __bfloat162float(h));
    }
}

// ---------------- tap-GEMM conv: NHWC bf16 hi/lo -> NHWC fp32 ----------------
// Block: 128 pixels x NFRAG*16 cols. 256 thr / 8 warps; warp owns 16 pixels.
// 9 taps x K/32 chunks, double-buffered cp.async. 3-pass bf16 split mma.
// smem stage (46080 B): Ah[128][40] Al[128][40] Bh[32][200] Bl[32][200]
template<int NFRAG>
__global__ __launch_bounds__(256, 1)
void conv_tap(const __nv_bfloat16* __restrict__ Xh,
              const __nv_bfloat16* __restrict__ Xl,
              const __nv_bfloat16* __restrict__ Bh,
              const __nv_bfloat16* __restrict__ Bl,
              float* __restrict__ Y, int K, int Neff)
{
    constexpr int NCOLS = NFRAG*16;
    constexpr int NSEG  = NCOLS/8;           // 16B segs per B row
    constexpr int STAGE = 46080;
    extern __shared__ char smc[];
    const uint32_t sb = (uint32_t)__cvta_generic_to_shared(smc);

    const int t   = threadIdx.x;
    const int wid = t >> 5;
    const int tb  = blockIdx.x * 128;        // global pixel base
    const int rb  = tb % HW;                 // row base within image
    const int nb  = blockIdx.y * NCOLS;
    const int kch = K >> 5;
    const int CC  = 9 * kch;

    wmma::fragment<wmma::accumulator,16,16,16,float> acc[NFRAG];
#pragma unroll
    for (int f = 0; f < NFRAG; ++f) wmma::fill_fragment(acc[f], 0.f);

    auto LOAD = [&](int cc, int buf) {
        const uint32_t st = sb + buf*STAGE;
        int tap = cc / kch;
        int k0  = (cc - tap*kch) << 5;
        int dh = tap/3 - 1, dw = tap - (tap/3)*3 - 1;
        // A: 128 rows x 4 segs x {hi,lo} = 1024 tasks
#pragma unroll
        for (int it = 0; it < 4; ++it) {
            int task = t + it*256;
            int half = task >> 9;
            int t2 = task & 511;
            int row = t2 >> 2, seg = t2 & 3;
            int r = rb + row;
            int h = r / 224;
            int w = r - h*224;
            bool ok = ((unsigned)(h+dh) < 128u) && ((unsigned)(w+dw) < 224u);
            size_t off = ok ? ((size_t)(tb + row + dh*224 + dw)*K + k0) : 0;
            const __nv_bfloat16* src = (half ? Xl : Xh) + off + seg*8;
            cp16(st + half*10240 + row*80 + seg*16, src, ok ? 16 : 0);
        }
        // B: 32 rows x NSEG segs x {hi,lo}
        const int BT = 32*NSEG;
#pragma unroll
        for (int it = 0; it < (2*BT + 255)/256; ++it) {
            int task = t + it*256;
            if (task < 2*BT) {
                int half = task >= BT;
                int tk = half ? task - BT : task;
                int row = tk / NSEG, seg = tk - row*NSEG;
                size_t off = (size_t)(tap*K + k0 + row)*Neff + nb + seg*8;
                const __nv_bfloat16* src = (half ? Bl : Bh) + off;
                cp16(st + 20480 + half*12800 + row*400 + seg*16, src, 16);
            }
        }
        CP_COMMIT();
    };

    LOAD(0, 0);
    for (int cc = 0; cc < CC; ++cc) {
        int cur = cc & 1;
        if (cc + 1 < CC) LOAD(cc+1, cur^1);
        else CP_COMMIT();                    // empty group keeps count aligned
        CP_WAIT1();
        __syncthreads();
        const __nv_bfloat16* Ah = (const __nv_bfloat16*)(smc + cur*STAGE);
        const __nv_bfloat16* Al = (const __nv_bfloat16*)(smc + cur*STAGE + 10240);
        const __nv_bfloat16* Bhs= (const __nv_bfloat16*)(smc + cur*STAGE + 20480);
        const __nv_bfloat16* Bls= (const __nv_bfloat16*)(smc + cur*STAGE + 33280);
#pragma unroll
        for (int ks = 0; ks < 2; ++ks) {
            wmma::fragment<wmma::matrix_a,16,16,16,__nv_bfloat16,wmma::row_major> ah, al;
            wmma::load_matrix_sync(ah, Ah + wid*16*40 + ks*16, 40);
            wmma::load_matrix_sync(al, Al + wid*16*40 + ks*16, 40);
#pragma unroll
            for (int f = 0; f < NFRAG; ++f) {
                wmma::fragment<wmma::matrix_b,16,16,16,__nv_bfloat16,wmma::row_major> bh, bl;
                wmma::load_matrix_sync(bh, Bhs + ks*16*200 + f*16, 200);
                wmma::load_matrix_sync(bl, Bls + ks*16*200 + f*16, 200);
                wmma::mma_sync(acc[f], ah, bh, acc[f]);
                wmma::mma_sync(acc[f], ah, bl, acc[f]);
                wmma::mma_sync(acc[f], al, bh, acc[f]);
            }
        }
        __syncthreads();
    }

    // epilogue: per-fragment wave through smem, coalesced NHWC float4 writes
    float* sD = (float*)smc;
#pragma unroll
    for (int g = 0; g < NFRAG; ++g) {
        wmma::store_matrix_sync(sD + wid*16*20, acc[g], 20, wmma::mem_row_major);
        __syncthreads();
#pragma unroll
        for (int it = 0; it < 2; ++it) {
            int task = t + it*256;
            int row = task >> 2, s4 = task & 3;
            float4 v = *(const float4*)(sD + row*20 + s4*4);
            *(float4*)(Y + (size_t)(tb+row)*Neff + nb + g*16 + s4*4) = v;
        }
        __syncthreads();
    }
}

// ---------------- BN stats over NHWC [P, C2] ---------------------------------
__global__ void bn_stats1(const float* __restrict__ Y, int C2,
                          float2* __restrict__ part)
{
    const int c = threadIdx.x;            // C2 threads
    const int by = blockIdx.x;            // 224 chunks x 512 pixels
    const float* p = Y + (size_t)by*512*C2 + c;
    float s = 0.f, q = 0.f;
#pragma unroll 8
    for (int i = 0; i < 512; ++i) {
        float v = p[(size_t)i*C2];
        s += v; q = fmaf(v, v, q);
    }
    part[c*224 + by] = make_float2(s, q);
}

__global__ void bn_stats2(const float2* __restrict__ part,
                          float* __restrict__ mean, float* __restrict__ rstd)
{
    const int c = threadIdx.x;
    double s = 0.0, q = 0.0;
    for (int i = 0; i < 224; ++i) {
        float2 v = part[c*224 + i];
        s += (double)v.x; q += (double)v.y;
    }
    double cnt = (double)PTOT;
    double m = s / cnt;
    double var = q / cnt - m*m;
    mean[c] = (float)m;
    rstd[c] = (float)(1.0 / sqrt(var + 1e-5));
}

// -------- BN apply + ReLU + split-bf16, NHWC fp32 -> NHWC bf16 hi/lo --------
__global__ void bn_apply(const float* __restrict__ Y, int C2,
                         const float* __restrict__ mean,
                         const float* __restrict__ rstd,
                         const float* __restrict__ g, const float* __restrict__ b,
                         __nv_bfloat16* __restrict__ Xh,
                         __nv_bfloat16* __restrict__ Xl)
{
    const int c = threadIdx.x;
    const int pb = blockIdx.x * 256;
    const float sc = rstd[c]*g[c>>1];
    const float bi = b[c>>1] - mean[c]*sc;
    for (int p = 0; p < 256; ++p) {
        size_t o = (size_t)(pb+p)*C2 + c;
        float v = fmaxf(fmaf(Y[o], sc, bi), 0.f);
        __nv_bfloat16 h = __float2bfloat16(v);
        Xh[o] = h;
        Xl[o] = __float2bfloat16(v - __bfloat162float(h));
    }
}

// -------- layer-4: BN + ReLU + |z|, NHWC [P,192] -> NCHW M [4,96,HW] --------
__global__ void bn_mag_t(const float* __restrict__ Y,
                         const float* __restrict__ mean,
                         const float* __restrict__ rstd,
                         const float* __restrict__ g, const float* __restrict__ b,
                         float* __restrict__ M)
{
    __shared__ float sM[96][65];
    const int t = threadIdx.x;
    const int gp = blockIdx.x * 64;
    const int n = gp / HW, rbas = gp % HW;
#pragma unroll
    for (int it = 0; it < 24; ++it) {
        int idx = t + it*256;
        int co = idx % 96, pp = idx / 96;
        float2 v = *(const float2*)(Y + (size_t)(gp+pp)*192 + 2*co);
        float scr = rstd[2*co]*g[co];
        float bir = b[co] - mean[2*co]*scr;
        float sci = rstd[2*co+1]*g[co];
        float bii = b[co] - mean[2*co+1]*sci;
        float a = fmaxf(fmaf(v.x, scr, bir), 0.f);
        float d = fmaxf(fmaf(v.y, sci, bii), 0.f);
        sM[co][pp] = sqrtf(a*a + d*d);
    }
    __syncthreads();
#pragma unroll
    for (int it = 0; it < 24; ++it) {
        int idx = t + it*256;
        int pp = idx & 63, co = idx >> 6;
        M[((size_t)(n*96 + co))*HW + rbas + pp] = sM[co][pp];
    }
}

// ---------------- head: 96 -> 3 channels (NCHW, scalar fp32) ----------------
__global__ __launch_bounds__(256)
void conv_head(const float* __restrict__ m,
               const float* __restrict__ wc, const float* __restrict__ bc,
               const float* __restrict__ wg, const float* __restrict__ bg,
               float* __restrict__ out)
{
    __shared__ float sm[18*35];
    __shared__ float sw[3*9];
    const int t = threadIdx.x;
    const int tx = t & 15, ty = t >> 4;
    const int wbase = blockIdx.x * 32, hbase = blockIdx.y * 16;
    const int n = blockIdx.z;

    float acc[3][2] = {};
    for (int ci = 0; ci < 96; ++ci) {
        const float* p = m + ((size_t)(n*96 + ci))*HW;
        for (int idx = t; idx < 18*34; idx += 256) {
            int r = idx / 34, c = idx - r*34;
            int gh = hbase - 1 + r, gw = wbase - 1 + c;
            sm[r*35 + c] = (((unsigned)gh < HH) && ((unsigned)gw < WW))
                           ? p[gh*WW + gw] : 0.f;
        }
        if (t < 27) {
            int co = t / 9, k = t - co*9;
            sw[t] = (co == 0) ? wc[(size_t)ci*9 + k]
                              : wg[((size_t)(co-1)*96 + ci)*9 + k];
        }
        __syncthreads();
#pragma unroll
        for (int kh = 0; kh < 3; ++kh)
#pragma unroll
            for (int kw = 0; kw < 3; ++kw) {
                float a0 = sm[(ty+kh)*35 + 2*tx + kw];
                float a1 = sm[(ty+kh)*35 + 2*tx + kw + 1];
#pragma unroll
                for (int co = 0; co < 3; ++co) {
                    float wv = sw[co*9 + kh*3 + kw];
                    acc[co][0] = fmaf(a0, wv, acc[co][0]);
                    acc[co][1] = fmaf(a1, wv, acc[co][1]);
                }
            }
        __syncthreads();
    }
    const int h = hbase + ty, w0 = wbase + 2*tx;
    const float b0 = bc[0], b1 = bg[0], b2 = bg[1];
    float c0a = acc[0][0] + b0, c0b = acc[0][1] + b0;
    c0a = 1.f / (1.f + expf(-c0a));
    c0b = 1.f / (1.f + expf(-c0b));
    size_t o0 = ((size_t)(n*3 + 0))*HW + h*WW + w0;
    size_t o1 = ((size_t)(n*3 + 1))*HW + h*WW + w0;
    size_t o2 = ((size_t)(n*3 + 2))*HW + h*WW + w0;
    out[o0] = c0a;            out[o0+1] = c0b;
    out[o1] = acc[1][0] + b1; out[o1+1] = acc[1][1] + b1;
    out[o2] = acc[2][0] + b2; out[o2+1] = acc[2][1] + b2;
}

// ---------------- driver -----------------------------------------------------
extern "C" void kernel_launch(void* const* d_in, const int* in_sizes, int n_in,
                              void* d_out, int out_size)
{
    (void)in_sizes; (void)n_in; (void)out_size;
    const float* x   = (const float*)d_in[0];
    const float* w1r = (const float*)d_in[1];
    const float* w1i = (const float*)d_in[2];
    const float* g1  = (const float*)d_in[3];
    const float* b1  = (const float*)d_in[4];
    const float* w2r = (const float*)d_in[5];
    const float* w2i = (const float*)d_in[6];
    const float* g2  = (const float*)d_in[7];
    const float* b2  = (const float*)d_in[8];
    const float* w3r = (const float*)d_in[9];
    const float* w3i = (const float*)d_in[10];
    const float* g3  = (const float*)d_in[11];
    const float* b3  = (const float*)d_in[12];
    const float* w4r = (const float*)d_in[13];
    const float* w4i = (const float*)d_in[14];
    const float* g4  = (const float*)d_in[15];
    const float* b4  = (const float*)d_in[16];
    const float* wc  = (const float*)d_in[17];
    const float* bc  = (const float*)d_in[18];
    const float* wg  = (const float*)d_in[19];
    const float* bg  = (const float*)d_in[20];
    float* out = (float*)d_out;

    float *Y, *M, *mean, *rstd;
    float2* part;
    __nv_bfloat16 *Xh, *Xl, *B1h, *B1l, *B2h, *B2l, *B3h, *B3l, *B4h, *B4l;
    cudaGetSymbolAddress((void**)&Y,   g_Y);
    cudaGetSymbolAddress((void**)&M,   g_M);
    cudaGetSymbolAddress((void**)&mean,g_mean);
    cudaGetSymbolAddress((void**)&rstd,g_rstd);
    cudaGetSymbolAddress((void**)&part,g_part);
    cudaGetSymbolAddress((void**)&Xh,  g_Xh);
    cudaGetSymbolAddress((void**)&Xl,  g_Xl);
    cudaGetSymbolAddress((void**)&B1h, g_B1h);
    cudaGetSymbolAddress((void**)&B1l, g_B1l);
    cudaGetSymbolAddress((void**)&B2h, g_B2h);
    cudaGetSymbolAddress((void**)&B2l, g_B2l);
    cudaGetSymbolAddress((void**)&B3h, g_B3h);
    cudaGetSymbolAddress((void**)&B3l, g_B3l);
    cudaGetSymbolAddress((void**)&B4h, g_B4h);
    cudaGetSymbolAddress((void**)&B4l, g_B4l);

    cudaFuncSetAttribute((const void*)conv_tap<9>,
                         cudaFuncAttributeMaxDynamicSharedMemorySize, 92160);
    cudaFuncSetAttribute((const void*)conv_tap<12>,
                         cudaFuncAttributeMaxDynamicSharedMemorySize, 92160);

    // weights + input layout
    build_real<<<(9*256*288 + 255)/256, 256>>>(w1r, w1i, B1h, B1l, 256, 144);
    build_cplx<<<(9*288*192 + 255)/256, 256>>>(w2r, w2i, B2h, B2l, 144, 96);
    build_cplx<<<(9*192*192 + 255)/256, 256>>>(w3r, w3i, B3h, B3l, 96, 96);
    build_cplx<<<(9*192*192 + 255)/256, 256>>>(w4r, w4i, B4h, B4l, 96, 96);
    tr_in<<<dim3(PTOT/64, 8), 256>>>(x, Xh, Xl);

    // Layer 1: K=256 real, Neff=288 (N split in 2)
    conv_tap<9><<<dim3(PTOT/128, 2), 256, 92160>>>(Xh, Xl, B1h, B1l, Y, 256, 288);
    bn_stats1<<<224, 288>>>(Y, 288, part);
    bn_stats2<<<1, 288>>>(part, mean, rstd);
    bn_apply<<<448, 288>>>(Y, 288, mean, rstd, g1, b1, Xh, Xl);

    // Layer 2: K=288, Neff=192
    conv_tap<12><<<dim3(PTOT/128, 1), 256, 92160>>>(Xh, Xl, B2h, B2l, Y, 288, 192);
    bn_stats1<<<224, 192>>>(Y, 192, part);
    bn_stats2<<<1, 192>>>(part, mean, rstd);
    bn_apply<<<448, 192>>>(Y, 192, mean, rstd, g2, b2, Xh, Xl);

    // Layer 3: K=192, Neff=192
    conv_tap<12><<<dim3(PTOT/128, 1), 256, 92160>>>(Xh, Xl, B3h, B3l, Y, 192, 192);
    bn_stats1<<<224, 192>>>(Y, 192, part);
    bn_stats2<<<1, 192>>>(part, mean, rstd);
    bn_apply<<<448, 192>>>(Y, 192, mean, rstd, g3, b3, Xh, Xl);

    // Layer 4: K=192, Neff=192, fused BN+ReLU+|z| + transpose to NCHW
    conv_tap<12><<<dim3(PTOT/128, 1), 256, 92160>>>(Xh, Xl, B4h, B4l, Y, 192, 192);
    bn_stats1<<<224, 192>>>(Y, 192, part);
    bn_stats2<<<1, 192>>>(part, mean, rstd);
    bn_mag_t<<<PTOT/64, 256>>>(Y, mean, rstd, g4, b4, M);

    // head (ch0 sigmoid)
    conv_head<<<dim3(7, 8, NN), 256>>>(M, wc, bc, wg, bg, out);
}